// round 2
// baseline (speedup 1.0000x reference)
#include <cuda_runtime.h>
#include <cuda_bf16.h>
#include <cstdint>

// NeuralCA: x(16,16,128,128), 24 steps, out (16,25,16,128,128) fp32.
// Step: depthwise [id, sobel_x, sobel_y] perception (wrap pad) -> per-pixel MLP
// 48->128(relu)->16 -> x += delta -> mask by (pre_alive & post_alive), where
// alive = maxpool3x3(ch0) > 0.1.
//
// Kernel A: perception + MLP + residual -> g_xmid, pre mask -> g_pre
// Kernel B: post alive from g_xmid ch0 neighborhood, apply mask, write frame t.

static constexpr int B_ = 16;
static constexpr int C_ = 16;
static constexpr int H_ = 128;
static constexpr int W_ = 128;
static constexpr int HID_ = 128;
static constexpr int STEPS_ = 24;   // setup_inputs() always passes steps=24
static constexpr int F_ = 3 * C_;   // 48 perception features
static constexpr float THR_ = 0.1f;

static constexpr int FRAME_ = C_ * H_ * W_;          // 262144
static constexpr int NPIX_  = B_ * H_ * W_;          // 262144

// Scratch (allowed: __device__ globals, no runtime allocation)
__device__ float         g_xmid[B_ * C_ * H_ * W_];
__device__ unsigned char g_pre[B_ * H_ * W_];

struct SmemA {
    float tile[C_][18][18];   // halo'd input tile
    float w1[HID_ * F_];      // w1[o*48+c]
    float b1[HID_];
    float w2t[HID_ * C_];     // transposed: w2t[o*16+k] = w2[k*128+o]
};

__global__ void copy_frame0_kernel(float* __restrict__ out, const float* __restrict__ x) {
    int idx = blockIdx.x * blockDim.x + threadIdx.x;
    if (idx >= B_ * FRAME_) return;
    int b = idx / FRAME_;
    int rem = idx - b * FRAME_;
    out[(size_t)b * (STEPS_ + 1) * FRAME_ + rem] = x[idx];
}

__global__ __launch_bounds__(256)
void step_kernel(const float* __restrict__ out_base, int t,
                 const float* __restrict__ w1,
                 const float* __restrict__ b1,
                 const float* __restrict__ w2) {
    extern __shared__ char smem_raw[];
    SmemA& s = *reinterpret_cast<SmemA*>(smem_raw);

    const int tid = threadIdx.x;
    const int bIdx = blockIdx.z;
    const int tileX = blockIdx.x;   // 0..7
    const int tileY = blockIdx.y;   // 0..7

    // previous (masked) frame lives in out[b][t-1]
    const float* prev = out_base + ((size_t)bIdx * (STEPS_ + 1) + (t - 1)) * FRAME_;

    // ---- cooperative loads ----
    // halo tile: 16 channels x 18x18 with wrap
    for (int i = tid; i < C_ * 18 * 18; i += 256) {
        int c = i / 324;
        int r = (i % 324) / 18;
        int col = i % 18;
        int gy = (tileY * 16 + r - 1 + H_) & (H_ - 1);
        int gx = (tileX * 16 + col - 1 + W_) & (W_ - 1);
        s.tile[c][r][col] = prev[(c * H_ + gy) * W_ + gx];
    }
    for (int i = tid; i < HID_ * F_; i += 256) s.w1[i] = w1[i];
    if (tid < HID_) s.b1[tid] = b1[tid];
    for (int i = tid; i < C_ * HID_; i += 256) {
        int k = i / HID_;
        int o = i - k * HID_;
        s.w2t[o * C_ + k] = w2[i];
    }
    __syncthreads();

    const int tx = tid & 15;
    const int ty = tid >> 4;

    // ---- perception: 48 features per pixel ----
    float f[F_];
    float premax = -3.0e38f;
#pragma unroll
    for (int c = 0; c < C_; c++) {
        float n00 = s.tile[c][ty    ][tx    ];
        float n01 = s.tile[c][ty    ][tx + 1];
        float n02 = s.tile[c][ty    ][tx + 2];
        float n10 = s.tile[c][ty + 1][tx    ];
        float n11 = s.tile[c][ty + 1][tx + 1];
        float n12 = s.tile[c][ty + 1][tx + 2];
        float n20 = s.tile[c][ty + 2][tx    ];
        float n21 = s.tile[c][ty + 2][tx + 1];
        float n22 = s.tile[c][ty + 2][tx + 2];
        f[3 * c + 0] = n11;
        // sobel_x = [[-1,0,1],[-2,0,2],[-1,0,1]]/8 (cross-correlation, XLA conv)
        f[3 * c + 1] = ((n02 - n00) + 2.0f * (n12 - n10) + (n22 - n20)) * 0.125f;
        // sobel_y = [[1,2,1],[0,0,0],[-1,-2,-1]]/8
        f[3 * c + 2] = (n00 + 2.0f * n01 + n02 - n20 - 2.0f * n21 - n22) * 0.125f;
        if (c == 0) {
            float m0 = fmaxf(fmaxf(n00, n01), fmaxf(n02, n10));
            float m1 = fmaxf(fmaxf(n11, n12), fmaxf(n20, n21));
            premax = fmaxf(fmaxf(m0, m1), n22);
        }
    }

    // ---- MLP 48 -> 128 (relu) -> 16 ----
    float acc[C_];
#pragma unroll
    for (int k = 0; k < C_; k++) acc[k] = 0.0f;

#pragma unroll 2
    for (int o = 0; o < HID_; o++) {
        float a = s.b1[o];
        const float* wr = &s.w1[o * F_];
#pragma unroll
        for (int c = 0; c < F_; c++) a = fmaf(f[c], wr[c], a);
        a = fmaxf(a, 0.0f);
        const float* w2r = &s.w2t[o * C_];
#pragma unroll
        for (int k = 0; k < C_; k++) acc[k] = fmaf(a, w2r[k], acc[k]);
    }

    // ---- residual + write scratch ----
    const int gy = tileY * 16 + ty;
    const int gx = tileX * 16 + tx;

    g_pre[(bIdx * H_ + gy) * W_ + gx] = (premax > THR_) ? 1 : 0;

    float* xm = g_xmid + (size_t)bIdx * FRAME_;
#pragma unroll
    for (int k = 0; k < C_; k++) {
        xm[(k * H_ + gy) * W_ + gx] = f[3 * k] + acc[k];
    }
}

__global__ __launch_bounds__(256)
void mask_kernel(float* __restrict__ out_base, int t) {
    int idx = blockIdx.x * blockDim.x + threadIdx.x;
    if (idx >= NPIX_) return;
    int b = idx >> 14;               // / (128*128)
    int rem = idx & 16383;
    int y = rem >> 7;
    int x = rem & 127;

    const float* xm = g_xmid + (size_t)b * FRAME_;   // channel 0 is at offset 0

    float m = -3.0e38f;
#pragma unroll
    for (int dy = -1; dy <= 1; dy++) {
        int yy = (y + dy + H_) & (H_ - 1);
#pragma unroll
        for (int dx = -1; dx <= 1; dx++) {
            int xx = (x + dx + W_) & (W_ - 1);
            m = fmaxf(m, xm[yy * W_ + xx]);
        }
    }
    bool post = m > THR_;
    bool alive = (g_pre[idx] != 0) && post;

    float* of = out_base + ((size_t)b * (STEPS_ + 1) + t) * FRAME_;
#pragma unroll
    for (int k = 0; k < C_; k++) {
        float v = xm[(k * H_ + y) * W_ + x];
        of[(k * H_ + y) * W_ + x] = alive ? v : 0.0f;
    }
}

extern "C" void kernel_launch(void* const* d_in, const int* in_sizes, int n_in,
                              void* d_out, int out_size) {
    const float* x  = (const float*)d_in[0];
    const float* w1 = (const float*)d_in[1];
    const float* b1 = (const float*)d_in[2];
    const float* w2 = (const float*)d_in[3];
    // d_in[4] = steps (always 24 for this problem instance)
    float* out = (float*)d_out;

    cudaFuncSetAttribute(step_kernel, cudaFuncAttributeMaxDynamicSharedMemorySize,
                         (int)sizeof(SmemA));

    copy_frame0_kernel<<<(B_ * FRAME_ + 255) / 256, 256>>>(out, x);

    for (int t = 1; t <= STEPS_; t++) {
        step_kernel<<<dim3(8, 8, B_), 256, sizeof(SmemA)>>>(out, t, w1, b1, w2);
        mask_kernel<<<(NPIX_ + 255) / 256, 256>>>(out, t);
    }
}

// round 3
// speedup vs baseline: 1.0821x; 1.0821x over previous
#include <cuda_runtime.h>
#include <cuda_bf16.h>
#include <cstdint>

// NeuralCA: x(16,16,128,128), 24 steps, out (16,25,16,128,128) fp32.
// Round 2: f32x2 packed-FMA MLP (halves fma-pipe issue slots), split
// accumulator chains (depth 48 -> 12), bias folded into chain init.

static constexpr int B_ = 16;
static constexpr int C_ = 16;
static constexpr int H_ = 128;
static constexpr int W_ = 128;
static constexpr int HID_ = 128;
static constexpr int STEPS_ = 24;
static constexpr int F_ = 3 * C_;   // 48
static constexpr float THR_ = 0.1f;

static constexpr int FRAME_ = C_ * H_ * W_;   // 262144
static constexpr int NPIX_  = B_ * H_ * W_;   // 262144

__device__ float         g_xmid[B_ * C_ * H_ * W_];
__device__ unsigned char g_pre[B_ * H_ * W_];

// ---- f32x2 helpers (Blackwell packed fp32) ----
__device__ __forceinline__ unsigned long long pk2(float lo, float hi) {
    unsigned long long r;
    asm("mov.b64 %0, {%1, %2};" : "=l"(r) : "f"(lo), "f"(hi));
    return r;
}
__device__ __forceinline__ void upk2(unsigned long long v, float& lo, float& hi) {
    asm("mov.b64 {%0, %1}, %2;" : "=f"(lo), "=f"(hi) : "l"(v));
}
__device__ __forceinline__ unsigned long long fma2(unsigned long long a,
                                                   unsigned long long b,
                                                   unsigned long long c) {
    unsigned long long d;
    asm("fma.rn.f32x2 %0, %1, %2, %3;" : "=l"(d) : "l"(a), "l"(b), "l"(c));
    return d;
}
__device__ __forceinline__ unsigned long long add2(unsigned long long a,
                                                   unsigned long long b) {
    unsigned long long d;
    asm("add.rn.f32x2 %0, %1, %2;" : "=l"(d) : "l"(a), "l"(b));
    return d;
}

struct SmemA {
    float tile[C_][18][18];             // 20736 B (multiple of 8)
    float w1[HID_ * F_];                // 24576 B, row o contiguous in c
    float b1[HID_];                     // 512 B
    unsigned long long w2p[64 * C_];    // 8192 B: w2p[op*16+k] = (w2[k][2op], w2[k][2op+1])
};

__global__ void copy_frame0_kernel(float* __restrict__ out, const float* __restrict__ x) {
    int idx = blockIdx.x * blockDim.x + threadIdx.x;
    if (idx >= B_ * FRAME_ / 4) return;
    int b = idx / (FRAME_ / 4);
    int rem = idx - b * (FRAME_ / 4);
    reinterpret_cast<float4*>(out + (size_t)b * (STEPS_ + 1) * FRAME_)[rem] =
        reinterpret_cast<const float4*>(x)[idx];
}

__global__ __launch_bounds__(256, 2)
void step_kernel(const float* __restrict__ out_base, int t,
                 const float* __restrict__ w1,
                 const float* __restrict__ b1,
                 const float* __restrict__ w2) {
    extern __shared__ char smem_raw[];
    SmemA& s = *reinterpret_cast<SmemA*>(smem_raw);

    const int tid = threadIdx.x;
    const int bIdx = blockIdx.z;
    const int tileX = blockIdx.x;
    const int tileY = blockIdx.y;

    const float* prev = out_base + ((size_t)bIdx * (STEPS_ + 1) + (t - 1)) * FRAME_;

    // ---- cooperative loads ----
    for (int i = tid; i < C_ * 18 * 18; i += 256) {
        int c = i / 324;
        int r = (i % 324) / 18;
        int col = i % 18;
        int gy = (tileY * 16 + r - 1 + H_) & (H_ - 1);
        int gx = (tileX * 16 + col - 1 + W_) & (W_ - 1);
        s.tile[c][r][col] = prev[(c * H_ + gy) * W_ + gx];
    }
    for (int i = tid; i < HID_ * F_; i += 256) s.w1[i] = w1[i];
    if (tid < HID_) s.b1[tid] = b1[tid];
    for (int i = tid; i < 64 * C_; i += 256) {
        int op = i >> 4;
        int k = i & 15;
        s.w2p[i] = pk2(w2[k * HID_ + 2 * op], w2[k * HID_ + 2 * op + 1]);
    }
    __syncthreads();

    const int tx = tid & 15;
    const int ty = tid >> 4;

    // ---- perception: 48 features, packed as 24 c-pairs ----
    unsigned long long fp2[F_ / 2];
    float premax = -3.0e38f;
    {
        float f[F_];
#pragma unroll
        for (int c = 0; c < C_; c++) {
            float n00 = s.tile[c][ty    ][tx    ];
            float n01 = s.tile[c][ty    ][tx + 1];
            float n02 = s.tile[c][ty    ][tx + 2];
            float n10 = s.tile[c][ty + 1][tx    ];
            float n11 = s.tile[c][ty + 1][tx + 1];
            float n12 = s.tile[c][ty + 1][tx + 2];
            float n20 = s.tile[c][ty + 2][tx    ];
            float n21 = s.tile[c][ty + 2][tx + 1];
            float n22 = s.tile[c][ty + 2][tx + 2];
            f[3 * c + 0] = n11;
            f[3 * c + 1] = ((n02 - n00) + 2.0f * (n12 - n10) + (n22 - n20)) * 0.125f;
            f[3 * c + 2] = (n00 + 2.0f * n01 + n02 - n20 - 2.0f * n21 - n22) * 0.125f;
            if (c == 0) {
                float m0 = fmaxf(fmaxf(n00, n01), fmaxf(n02, n10));
                float m1 = fmaxf(fmaxf(n11, n12), fmaxf(n20, n21));
                premax = fmaxf(fmaxf(m0, m1), n22);
            }
        }
#pragma unroll
        for (int cp = 0; cp < F_ / 2; cp++)
            fp2[cp] = pk2(f[2 * cp], f[2 * cp + 1]);
    }

    // ---- MLP 48 -> 128(relu) -> 16, all f32x2 ----
    unsigned long long acc2[C_];
#pragma unroll
    for (int k = 0; k < C_; k++) acc2[k] = 0ull;

    const unsigned long long* w1u = reinterpret_cast<const unsigned long long*>(s.w1);

#pragma unroll 4
    for (int op = 0; op < HID_ / 2; op++) {
        float h0, h1;
#pragma unroll
        for (int j = 0; j < 2; j++) {
            const int o = 2 * op + j;
            const unsigned long long* wr = w1u + o * (F_ / 2);
            unsigned long long a0 = pk2(s.b1[o], 0.0f);
            unsigned long long a1 = 0ull;
#pragma unroll
            for (int cp = 0; cp < F_ / 2; cp += 2) {
                a0 = fma2(fp2[cp],     wr[cp],     a0);
                a1 = fma2(fp2[cp + 1], wr[cp + 1], a1);
            }
            float lo, hi;
            upk2(add2(a0, a1), lo, hi);
            float h = fmaxf(lo + hi, 0.0f);
            if (j == 0) h0 = h; else h1 = h;
        }
        unsigned long long ap = pk2(h0, h1);
        const unsigned long long* w2r = &s.w2p[op * C_];
#pragma unroll
        for (int k = 0; k < C_; k++)
            acc2[k] = fma2(ap, w2r[k], acc2[k]);
    }

    // ---- residual + write scratch ----
    const int gy = tileY * 16 + ty;
    const int gx = tileX * 16 + tx;

    g_pre[(bIdx * H_ + gy) * W_ + gx] = (premax > THR_) ? 1 : 0;

    float* xm = g_xmid + (size_t)bIdx * FRAME_;
#pragma unroll
    for (int k = 0; k < C_; k++) {
        float lo, hi;
        upk2(acc2[k], lo, hi);
        // identity feature = center pixel, reload from smem (cheap, frees regs)
        float ident = s.tile[k][ty + 1][tx + 1];
        xm[(k * H_ + gy) * W_ + gx] = ident + lo + hi;
    }
}

__global__ __launch_bounds__(256)
void mask_kernel(float* __restrict__ out_base, int t) {
    int idx = blockIdx.x * blockDim.x + threadIdx.x;
    if (idx >= NPIX_) return;
    int b = idx >> 14;
    int rem = idx & 16383;
    int y = rem >> 7;
    int x = rem & 127;

    const float* xm = g_xmid + (size_t)b * FRAME_;

    float m = -3.0e38f;
#pragma unroll
    for (int dy = -1; dy <= 1; dy++) {
        int yy = (y + dy + H_) & (H_ - 1);
#pragma unroll
        for (int dx = -1; dx <= 1; dx++) {
            int xx = (x + dx + W_) & (W_ - 1);
            m = fmaxf(m, xm[yy * W_ + xx]);
        }
    }
    bool alive = (g_pre[idx] != 0) && (m > THR_);

    float* of = out_base + ((size_t)b * (STEPS_ + 1) + t) * FRAME_;
#pragma unroll
    for (int k = 0; k < C_; k++) {
        float v = xm[(k * H_ + y) * W_ + x];
        of[(k * H_ + y) * W_ + x] = alive ? v : 0.0f;
    }
}

extern "C" void kernel_launch(void* const* d_in, const int* in_sizes, int n_in,
                              void* d_out, int out_size) {
    const float* x  = (const float*)d_in[0];
    const float* w1 = (const float*)d_in[1];
    const float* b1 = (const float*)d_in[2];
    const float* w2 = (const float*)d_in[3];
    float* out = (float*)d_out;

    cudaFuncSetAttribute(step_kernel, cudaFuncAttributeMaxDynamicSharedMemorySize,
                         (int)sizeof(SmemA));

    copy_frame0_kernel<<<(B_ * FRAME_ / 4 + 255) / 256, 256>>>(out, x);

    for (int t = 1; t <= STEPS_; t++) {
        step_kernel<<<dim3(8, 8, B_), 256, sizeof(SmemA)>>>(out, t, w1, b1, w2);
        mask_kernel<<<(NPIX_ + 255) / 256, 256>>>(out, t);
    }
}

// round 5
// speedup vs baseline: 1.3575x; 1.2546x over previous
#include <cuda_runtime.h>
#include <cuda_bf16.h>
#include <cstdint>

// NeuralCA: x(16,16,128,128), 24 steps, out (16,25,16,128,128) fp32.
// Round 3: LDS.128 weight loads (ulonglong2 = 2x f32x2 per load) + 2 pixels
// per thread so each weight load feeds 4 fma2. Targets the L1/LDS bottleneck
// ncu showed (L1=87%), FMA floor ~59us/step.

static constexpr int B_ = 16;
static constexpr int C_ = 16;
static constexpr int H_ = 128;
static constexpr int W_ = 128;
static constexpr int HID_ = 128;
static constexpr int STEPS_ = 24;
static constexpr int F_ = 3 * C_;   // 48
static constexpr float THR_ = 0.1f;

static constexpr int FRAME_ = C_ * H_ * W_;   // 262144
static constexpr int NPIX_  = B_ * H_ * W_;   // 262144

__device__ float         g_xmid[B_ * C_ * H_ * W_];
__device__ unsigned char g_pre[B_ * H_ * W_];

typedef unsigned long long u64;

// ---- f32x2 helpers (Blackwell packed fp32) ----
__device__ __forceinline__ u64 pk2(float lo, float hi) {
    u64 r;
    asm("mov.b64 %0, {%1, %2};" : "=l"(r) : "f"(lo), "f"(hi));
    return r;
}
__device__ __forceinline__ void upk2(u64 v, float& lo, float& hi) {
    asm("mov.b64 {%0, %1}, %2;" : "=f"(lo), "=f"(hi) : "l"(v));
}
__device__ __forceinline__ u64 fma2(u64 a, u64 b, u64 c) {
    u64 d;
    asm("fma.rn.f32x2 %0, %1, %2, %3;" : "=l"(d) : "l"(a), "l"(b), "l"(c));
    return d;
}
__device__ __forceinline__ u64 add2(u64 a, u64 b) {
    u64 d;
    asm("add.rn.f32x2 %0, %1, %2;" : "=l"(d) : "l"(a), "l"(b));
    return d;
}

struct alignas(16) SmemA {
    float w1[HID_ * F_];      // 24576 B; row o = 48 floats = 24 u64 = 12 x 16B
    u64   w2p[64 * C_];       // 8192 B: w2p[op*16+k] = (w2[k][2op], w2[k][2op+1])
    float b1[HID_];           // 512 B
    float tile[C_][18][18];   // 20736 B
};

__global__ void copy_frame0_kernel(float* __restrict__ out, const float* __restrict__ x) {
    int idx = blockIdx.x * blockDim.x + threadIdx.x;
    if (idx >= B_ * FRAME_ / 4) return;
    int b = idx / (FRAME_ / 4);
    int rem = idx - b * (FRAME_ / 4);
    reinterpret_cast<float4*>(out + (size_t)b * (STEPS_ + 1) * FRAME_)[rem] =
        reinterpret_cast<const float4*>(x)[idx];
}

__global__ __launch_bounds__(128, 2)
void step_kernel(const float* __restrict__ out_base, int t,
                 const float* __restrict__ w1,
                 const float* __restrict__ b1,
                 const float* __restrict__ w2) {
    extern __shared__ char smem_raw[];
    SmemA& s = *reinterpret_cast<SmemA*>(smem_raw);

    const int tid = threadIdx.x;
    const int bIdx = blockIdx.z;
    const int tileX = blockIdx.x;
    const int tileY = blockIdx.y;

    const float* prev = out_base + ((size_t)bIdx * (STEPS_ + 1) + (t - 1)) * FRAME_;

    // ---- cooperative loads (128 threads) ----
    for (int i = tid; i < C_ * 18 * 18; i += 128) {
        int c = i / 324;
        int r = (i % 324) / 18;
        int col = i % 18;
        int gy = (tileY * 16 + r - 1 + H_) & (H_ - 1);
        int gx = (tileX * 16 + col - 1 + W_) & (W_ - 1);
        s.tile[c][r][col] = prev[(c * H_ + gy) * W_ + gx];
    }
    for (int i = tid; i < HID_ * F_; i += 128) s.w1[i] = w1[i];
    if (tid < HID_) s.b1[tid] = b1[tid];
    for (int i = tid; i < 64 * C_; i += 128) {
        int op = i >> 4;
        int k = i & 15;
        s.w2p[i] = pk2(w2[k * HID_ + 2 * op], w2[k * HID_ + 2 * op + 1]);
    }
    __syncthreads();

    const int tx = tid & 15;
    const int ty0 = tid >> 4;          // 0..7; this thread handles rows ty0 and ty0+8

    // ---- perception for both pixels: 48 features each, packed in 24 u64 ----
    u64 fp2[2][F_ / 2];
    float premax[2];
#pragma unroll
    for (int p = 0; p < 2; p++) {
        const int ty = ty0 + p * 8;
        float f[F_];
#pragma unroll
        for (int c = 0; c < C_; c++) {
            float n00 = s.tile[c][ty    ][tx    ];
            float n01 = s.tile[c][ty    ][tx + 1];
            float n02 = s.tile[c][ty    ][tx + 2];
            float n10 = s.tile[c][ty + 1][tx    ];
            float n11 = s.tile[c][ty + 1][tx + 1];
            float n12 = s.tile[c][ty + 1][tx + 2];
            float n20 = s.tile[c][ty + 2][tx    ];
            float n21 = s.tile[c][ty + 2][tx + 1];
            float n22 = s.tile[c][ty + 2][tx + 2];
            f[3 * c + 0] = n11;
            f[3 * c + 1] = ((n02 - n00) + 2.0f * (n12 - n10) + (n22 - n20)) * 0.125f;
            f[3 * c + 2] = (n00 + 2.0f * n01 + n02 - n20 - 2.0f * n21 - n22) * 0.125f;
            if (c == 0) {
                float m0 = fmaxf(fmaxf(n00, n01), fmaxf(n02, n10));
                float m1 = fmaxf(fmaxf(n11, n12), fmaxf(n20, n21));
                premax[p] = fmaxf(fmaxf(m0, m1), n22);
            }
        }
#pragma unroll
        for (int cp = 0; cp < F_ / 2; cp++)
            fp2[p][cp] = pk2(f[2 * cp], f[2 * cp + 1]);
    }

    // ---- MLP 48 -> 128(relu) -> 16, f32x2, weights via LDS.128 ----
    u64 acc2[2][C_];
#pragma unroll
    for (int p = 0; p < 2; p++)
#pragma unroll
        for (int k = 0; k < C_; k++) acc2[p][k] = 0ull;

#pragma unroll 2
    for (int op = 0; op < HID_ / 2; op++) {
        float h[2][2];
#pragma unroll
        for (int j = 0; j < 2; j++) {
            const int o = 2 * op + j;
            const ulonglong2* wr = reinterpret_cast<const ulonglong2*>(
                s.w1 + o * F_);                     // 12 x 16B per row
            u64 bini = pk2(s.b1[o], 0.0f);
            u64 a0[2] = {bini, bini};
            u64 a1[2] = {0ull, 0ull};
#pragma unroll
            for (int q = 0; q < 12; q++) {
                ulonglong2 wq = wr[q];              // one LDS.128 -> 4 fma2
                a0[0] = fma2(fp2[0][2 * q    ], wq.x, a0[0]);
                a1[0] = fma2(fp2[0][2 * q + 1], wq.y, a1[0]);
                a0[1] = fma2(fp2[1][2 * q    ], wq.x, a0[1]);
                a1[1] = fma2(fp2[1][2 * q + 1], wq.y, a1[1]);
            }
#pragma unroll
            for (int p = 0; p < 2; p++) {
                float lo, hi;
                upk2(add2(a0[p], a1[p]), lo, hi);
                h[p][j] = fmaxf(lo + hi, 0.0f);
            }
        }
        u64 ap0 = pk2(h[0][0], h[0][1]);
        u64 ap1 = pk2(h[1][0], h[1][1]);
        const ulonglong2* w2r = reinterpret_cast<const ulonglong2*>(
            &s.w2p[op * C_]);                       // 8 x 16B
#pragma unroll
        for (int kq = 0; kq < 8; kq++) {
            ulonglong2 wq = w2r[kq];                // one LDS.128 -> 4 fma2
            acc2[0][2 * kq    ] = fma2(ap0, wq.x, acc2[0][2 * kq    ]);
            acc2[0][2 * kq + 1] = fma2(ap0, wq.y, acc2[0][2 * kq + 1]);
            acc2[1][2 * kq    ] = fma2(ap1, wq.x, acc2[1][2 * kq    ]);
            acc2[1][2 * kq + 1] = fma2(ap1, wq.y, acc2[1][2 * kq + 1]);
        }
    }

    // ---- residual + write scratch (both pixels) ----
    const int gx = tileX * 16 + tx;
    float* xm = g_xmid + (size_t)bIdx * FRAME_;

#pragma unroll
    for (int p = 0; p < 2; p++) {
        const int ty = ty0 + p * 8;
        const int gy = tileY * 16 + ty;
        g_pre[(bIdx * H_ + gy) * W_ + gx] = (premax[p] > THR_) ? 1 : 0;
#pragma unroll
        for (int k = 0; k < C_; k++) {
            float lo, hi;
            upk2(acc2[p][k], lo, hi);
            float ident = s.tile[k][ty + 1][tx + 1];
            xm[(k * H_ + gy) * W_ + gx] = ident + lo + hi;
        }
    }
}

__global__ __launch_bounds__(256)
void mask_kernel(float* __restrict__ out_base, int t) {
    int idx = blockIdx.x * blockDim.x + threadIdx.x;
    if (idx >= NPIX_) return;
    int b = idx >> 14;
    int rem = idx & 16383;
    int y = rem >> 7;
    int x = rem & 127;

    const float* xm = g_xmid + (size_t)b * FRAME_;

    float m = -3.0e38f;
#pragma unroll
    for (int dy = -1; dy <= 1; dy++) {
        int yy = (y + dy + H_) & (H_ - 1);
#pragma unroll
        for (int dx = -1; dx <= 1; dx++) {
            int xx = (x + dx + W_) & (W_ - 1);
            m = fmaxf(m, xm[yy * W_ + xx]);
        }
    }
    bool alive = (g_pre[idx] != 0) && (m > THR_);

    float* of = out_base + ((size_t)b * (STEPS_ + 1) + t) * FRAME_;
#pragma unroll
    for (int k = 0; k < C_; k++) {
        float v = xm[(k * H_ + y) * W_ + x];
        of[(k * H_ + y) * W_ + x] = alive ? v : 0.0f;
    }
}

extern "C" void kernel_launch(void* const* d_in, const int* in_sizes, int n_in,
                              void* d_out, int out_size) {
    const float* x  = (const float*)d_in[0];
    const float* w1 = (const float*)d_in[1];
    const float* b1 = (const float*)d_in[2];
    const float* w2 = (const float*)d_in[3];
    float* out = (float*)d_out;

    cudaFuncSetAttribute(step_kernel, cudaFuncAttributeMaxDynamicSharedMemorySize,
                         (int)sizeof(SmemA));

    copy_frame0_kernel<<<(B_ * FRAME_ / 4 + 255) / 256, 256>>>(out, x);

    for (int t = 1; t <= STEPS_; t++) {
        step_kernel<<<dim3(8, 8, B_), 128, sizeof(SmemA)>>>(out, t, w1, b1, w2);
        mask_kernel<<<(NPIX_ + 255) / 256, 256>>>(out, t);
    }
}

// round 10
// speedup vs baseline: 1.3813x; 1.0175x over previous
#include <cuda_runtime.h>
#include <cuda_bf16.h>
#include <cstdint>

// NeuralCA: x(16,16,128,128), 24 steps, out (16,25,16,128,128) fp32.
// Round 5: register-pressure relief to let ptxas batch LDS.128 weight loads:
//  - second-layer accumulators packed by OUTPUT pair (acc regs 64->32, no
//    cross-lane reduce in epilogue)
//  - explicit half-row weight staging (6x ulonglong2 buffers) so loads run
//    ahead of the fma2 blocks
// Goal: push fma2 issue from 0.24 -> ~0.4 /cyc/SMSP (pipe ceiling 0.5).

static constexpr int B_ = 16;
static constexpr int C_ = 16;
static constexpr int H_ = 128;
static constexpr int W_ = 128;
static constexpr int HID_ = 128;
static constexpr int STEPS_ = 24;
static constexpr int F_ = 3 * C_;   // 48
static constexpr float THR_ = 0.1f;

static constexpr int FRAME_ = C_ * H_ * W_;   // 262144
static constexpr int NPIX_  = B_ * H_ * W_;   // 262144

__device__ float         g_xmid[B_ * C_ * H_ * W_];
__device__ unsigned char g_pre[B_ * H_ * W_];

typedef unsigned long long u64;

// ---- f32x2 helpers (Blackwell packed fp32) ----
__device__ __forceinline__ u64 pk2(float lo, float hi) {
    u64 r;
    asm("mov.b64 %0, {%1, %2};" : "=l"(r) : "f"(lo), "f"(hi));
    return r;
}
__device__ __forceinline__ void upk2(u64 v, float& lo, float& hi) {
    asm("mov.b64 {%0, %1}, %2;" : "=f"(lo), "=f"(hi) : "l"(v));
}
__device__ __forceinline__ u64 fma2(u64 a, u64 b, u64 c) {
    u64 d;
    asm("fma.rn.f32x2 %0, %1, %2, %3;" : "=l"(d) : "l"(a), "l"(b), "l"(c));
    return d;
}
__device__ __forceinline__ u64 add2(u64 a, u64 b) {
    u64 d;
    asm("add.rn.f32x2 %0, %1, %2;" : "=l"(d) : "l"(a), "l"(b));
    return d;
}

struct alignas(16) SmemA {
    float w1[HID_ * F_];      // 24576 B; row o = 48 floats = 12 x 16B
    u64   w2d[HID_ * 8];      // 8192 B: w2d[o*8+kq] = (w2[2kq][o], w2[2kq+1][o])
    float b1[HID_];           // 512 B
    float tile[C_][18][18];   // 20736 B
};

__global__ void copy_frame0_kernel(float* __restrict__ out, const float* __restrict__ x) {
    int idx = blockIdx.x * blockDim.x + threadIdx.x;
    if (idx >= B_ * FRAME_ / 4) return;
    int b = idx / (FRAME_ / 4);
    int rem = idx - b * (FRAME_ / 4);
    reinterpret_cast<float4*>(out + (size_t)b * (STEPS_ + 1) * FRAME_)[rem] =
        reinterpret_cast<const float4*>(x)[idx];
}

__global__ __launch_bounds__(128, 2)
void step_kernel(const float* __restrict__ out_base, int t,
                 const float* __restrict__ w1,
                 const float* __restrict__ b1,
                 const float* __restrict__ w2) {
    extern __shared__ char smem_raw[];
    SmemA& s = *reinterpret_cast<SmemA*>(smem_raw);

    const int tid = threadIdx.x;
    const int bIdx = blockIdx.z;
    const int tileX = blockIdx.x;
    const int tileY = blockIdx.y;

    const float* prev = out_base + ((size_t)bIdx * (STEPS_ + 1) + (t - 1)) * FRAME_;

    // ---- cooperative loads (128 threads) ----
    for (int i = tid; i < C_ * 18 * 18; i += 128) {
        int c = i / 324;
        int r = (i % 324) / 18;
        int col = i % 18;
        int gy = (tileY * 16 + r - 1 + H_) & (H_ - 1);
        int gx = (tileX * 16 + col - 1 + W_) & (W_ - 1);
        s.tile[c][r][col] = prev[(c * H_ + gy) * W_ + gx];
    }
    for (int i = tid; i < HID_ * F_; i += 128) s.w1[i] = w1[i];
    if (tid < HID_) s.b1[tid] = b1[tid];
    // w2d[o*8+kq] = (w2[2kq][o], w2[2kq+1][o]); w2 is [k*128+o]
    for (int i = tid; i < HID_ * 8; i += 128) {
        int o = i >> 3;
        int kq = i & 7;
        s.w2d[i] = pk2(w2[(2 * kq) * HID_ + o], w2[(2 * kq + 1) * HID_ + o]);
    }
    __syncthreads();

    const int tx = tid & 15;
    const int ty0 = tid >> 4;          // rows ty0 and ty0+8

    // ---- perception for both pixels ----
    u64 fp2[2][F_ / 2];
    float premax[2];
#pragma unroll
    for (int p = 0; p < 2; p++) {
        const int ty = ty0 + p * 8;
        float f[F_];
#pragma unroll
        for (int c = 0; c < C_; c++) {
            float n00 = s.tile[c][ty    ][tx    ];
            float n01 = s.tile[c][ty    ][tx + 1];
            float n02 = s.tile[c][ty    ][tx + 2];
            float n10 = s.tile[c][ty + 1][tx    ];
            float n12 = s.tile[c][ty + 1][tx + 2];
            float n20 = s.tile[c][ty + 2][tx    ];
            float n21 = s.tile[c][ty + 2][tx + 1];
            float n22 = s.tile[c][ty + 2][tx + 2];
            f[3 * c + 0] = s.tile[c][ty + 1][tx + 1];
            f[3 * c + 1] = ((n02 - n00) + 2.0f * (n12 - n10) + (n22 - n20)) * 0.125f;
            f[3 * c + 2] = (n00 + 2.0f * n01 + n02 - n20 - 2.0f * n21 - n22) * 0.125f;
            if (c == 0) {
                float m0 = fmaxf(fmaxf(n00, n01), fmaxf(n02, n10));
                float m1 = fmaxf(fmaxf(f[0], n12), fmaxf(n20, n21));
                premax[p] = fmaxf(fmaxf(m0, m1), n22);
            }
        }
#pragma unroll
        for (int cp = 0; cp < F_ / 2; cp++)
            fp2[p][cp] = pk2(f[2 * cp], f[2 * cp + 1]);
    }

    // ---- MLP 48 -> 128(relu) -> 16 ----
    // acc2[p][kq] lanes = (output 2kq, output 2kq+1); full sums, no reduce.
    u64 acc2[2][8];
#pragma unroll
    for (int p = 0; p < 2; p++)
#pragma unroll
        for (int kq = 0; kq < 8; kq++) acc2[p][kq] = 0ull;

#pragma unroll 2
    for (int op = 0; op < HID_ / 2; op++) {
        float h[2][2];   // h[j][p]
#pragma unroll
        for (int j = 0; j < 2; j++) {
            const int o = 2 * op + j;
            const ulonglong2* wr = reinterpret_cast<const ulonglong2*>(s.w1 + o * F_);
            // stage first half-row
            ulonglong2 wa[6];
#pragma unroll
            for (int q = 0; q < 6; q++) wa[q] = wr[q];
            u64 bini = pk2(s.b1[o], 0.0f);
            u64 a0[2] = {bini, bini};
            u64 a1[2] = {0ull, 0ull};
            // stage second half-row before consuming the first
            ulonglong2 wb[6];
#pragma unroll
            for (int q = 0; q < 6; q++) wb[q] = wr[q + 6];
#pragma unroll
            for (int q = 0; q < 6; q++) {
                a0[0] = fma2(fp2[0][2 * q    ], wa[q].x, a0[0]);
                a1[0] = fma2(fp2[0][2 * q + 1], wa[q].y, a1[0]);
                a0[1] = fma2(fp2[1][2 * q    ], wa[q].x, a0[1]);
                a1[1] = fma2(fp2[1][2 * q + 1], wa[q].y, a1[1]);
            }
#pragma unroll
            for (int q = 0; q < 6; q++) {
                a0[0] = fma2(fp2[0][12 + 2 * q], wb[q].x, a0[0]);
                a1[0] = fma2(fp2[0][13 + 2 * q], wb[q].y, a1[0]);
                a0[1] = fma2(fp2[1][12 + 2 * q], wb[q].x, a0[1]);
                a1[1] = fma2(fp2[1][13 + 2 * q], wb[q].y, a1[1]);
            }
#pragma unroll
            for (int p = 0; p < 2; p++) {
                float lo, hi;
                upk2(add2(a0[p], a1[p]), lo, hi);
                h[j][p] = fmaxf(lo + hi, 0.0f);
            }
        }
        // second layer: for each of the two hidden units, 4 LDS.128 + 8 fma2/px
#pragma unroll
        for (int j = 0; j < 2; j++) {
            const int o = 2 * op + j;
            const ulonglong2* w2r = reinterpret_cast<const ulonglong2*>(s.w2d + o * 8);
            ulonglong2 wk[4];
#pragma unroll
            for (int q = 0; q < 4; q++) wk[q] = w2r[q];
            u64 hd0 = pk2(h[j][0], h[j][0]);
            u64 hd1 = pk2(h[j][1], h[j][1]);
#pragma unroll
            for (int q = 0; q < 4; q++) {
                acc2[0][2 * q    ] = fma2(hd0, wk[q].x, acc2[0][2 * q    ]);
                acc2[0][2 * q + 1] = fma2(hd0, wk[q].y, acc2[0][2 * q + 1]);
                acc2[1][2 * q    ] = fma2(hd1, wk[q].x, acc2[1][2 * q    ]);
                acc2[1][2 * q + 1] = fma2(hd1, wk[q].y, acc2[1][2 * q + 1]);
            }
        }
    }

    // ---- residual + write scratch (both pixels) ----
    const int gx = tileX * 16 + tx;
    float* xm = g_xmid + (size_t)bIdx * FRAME_;

#pragma unroll
    for (int p = 0; p < 2; p++) {
        const int ty = ty0 + p * 8;
        const int gy = tileY * 16 + ty;
        g_pre[(bIdx * H_ + gy) * W_ + gx] = (premax[p] > THR_) ? 1 : 0;
#pragma unroll
        for (int kq = 0; kq < 8; kq++) {
            float d0, d1;
            upk2(acc2[p][kq], d0, d1);
            float i0 = s.tile[2 * kq    ][ty + 1][tx + 1];
            float i1 = s.tile[2 * kq + 1][ty + 1][tx + 1];
            xm[((2 * kq    ) * H_ + gy) * W_ + gx] = i0 + d0;
            xm[((2 * kq + 1) * H_ + gy) * W_ + gx] = i1 + d1;
        }
    }
}

__global__ __launch_bounds__(256)
void mask_kernel(float* __restrict__ out_base, int t) {
    int idx = blockIdx.x * blockDim.x + threadIdx.x;
    if (idx >= NPIX_) return;
    int b = idx >> 14;
    int rem = idx & 16383;
    int y = rem >> 7;
    int x = rem & 127;

    const float* xm = g_xmid + (size_t)b * FRAME_;

    float m = -3.0e38f;
#pragma unroll
    for (int dy = -1; dy <= 1; dy++) {
        int yy = (y + dy + H_) & (H_ - 1);
#pragma unroll
        for (int dx = -1; dx <= 1; dx++) {
            int xx = (x + dx + W_) & (W_ - 1);
            m = fmaxf(m, xm[yy * W_ + xx]);
        }
    }
    bool alive = (g_pre[idx] != 0) && (m > THR_);

    float* of = out_base + ((size_t)b * (STEPS_ + 1) + t) * FRAME_;
#pragma unroll
    for (int k = 0; k < C_; k++) {
        float v = xm[(k * H_ + y) * W_ + x];
        of[(k * H_ + y) * W_ + x] = alive ? v : 0.0f;
    }
}

extern "C" void kernel_launch(void* const* d_in, const int* in_sizes, int n_in,
                              void* d_out, int out_size) {
    const float* x  = (const float*)d_in[0];
    const float* w1 = (const float*)d_in[1];
    const float* b1 = (const float*)d_in[2];
    const float* w2 = (const float*)d_in[3];
    float* out = (float*)d_out;

    cudaFuncSetAttribute(step_kernel, cudaFuncAttributeMaxDynamicSharedMemorySize,
                         (int)sizeof(SmemA));

    copy_frame0_kernel<<<(B_ * FRAME_ / 4 + 255) / 256, 256>>>(out, x);

    for (int t = 1; t <= STEPS_; t++) {
        step_kernel<<<dim3(8, 8, B_), 128, sizeof(SmemA)>>>(out, t, w1, b1, w2);
        mask_kernel<<<(NPIX_ + 255) / 256, 256>>>(out, t);
    }
}